// round 8
// baseline (speedup 1.0000x reference)
#include <cuda_runtime.h>
#include <math_constants.h>

#define NROWS 4096
#define M_REC 4000
#define M_SUB 20000
#define MAXG  10

// Scratch (allocation-free per harness rules)
__device__ int   g_ri[NROWS];
__device__ int   g_si[NROWS];
__device__ float g_pself[NROWS];

// ---------------------------------------------------------------------------
// Row argmax: one block per row, float4 vectorized, streaming loads (.cs:
// data is read exactly once), 8-deep independent load batch for MLP.
// Scan carries only (best value, best VECTOR index); lane within the winning
// vector recovered post-scan with one (cache-hot) reload, exact bit equality.
// Tie-break: first (smallest) index, matching jnp.argmax.
// ---------------------------------------------------------------------------
template <int M>
__device__ __forceinline__ void row_argmax(const float* __restrict__ mat,
                                           int row, int* __restrict__ out_idx)
{
    const float4* __restrict__ rp =
        reinterpret_cast<const float4*>(mat + (size_t)row * M);
    constexpr int M4 = M / 4;   // both 4000 and 20000 divisible by 4

    float best = -CUDART_INF_F;
    int   bvec = (threadIdx.x < M4) ? (int)threadIdx.x : 0;

    int i = threadIdx.x;
    // Tier 1: 8 independent streaming float4 loads in flight (128 B/thread)
    for (; i + 7 * 256 < M4; i += 8 * 256) {
        float4 v0 = __ldcs(&rp[i]);
        float4 v1 = __ldcs(&rp[i +  256]);
        float4 v2 = __ldcs(&rp[i +  512]);
        float4 v3 = __ldcs(&rp[i +  768]);
        float4 v4 = __ldcs(&rp[i + 1024]);
        float4 v5 = __ldcs(&rp[i + 1280]);
        float4 v6 = __ldcs(&rp[i + 1536]);
        float4 v7 = __ldcs(&rp[i + 1792]);
        float m0 = fmaxf(fmaxf(v0.x, v0.y), fmaxf(v0.z, v0.w));
        float m1 = fmaxf(fmaxf(v1.x, v1.y), fmaxf(v1.z, v1.w));
        float m2 = fmaxf(fmaxf(v2.x, v2.y), fmaxf(v2.z, v2.w));
        float m3 = fmaxf(fmaxf(v3.x, v3.y), fmaxf(v3.z, v3.w));
        float m4 = fmaxf(fmaxf(v4.x, v4.y), fmaxf(v4.z, v4.w));
        float m5 = fmaxf(fmaxf(v5.x, v5.y), fmaxf(v5.z, v5.w));
        float m6 = fmaxf(fmaxf(v6.x, v6.y), fmaxf(v6.z, v6.w));
        float m7 = fmaxf(fmaxf(v7.x, v7.y), fmaxf(v7.z, v7.w));
        // strict '>' keeps the earliest vector on ties (ascending visit order)
        if (m0 > best) { best = m0; bvec = i;        }
        if (m1 > best) { best = m1; bvec = i +  256; }
        if (m2 > best) { best = m2; bvec = i +  512; }
        if (m3 > best) { best = m3; bvec = i +  768; }
        if (m4 > best) { best = m4; bvec = i + 1024; }
        if (m5 > best) { best = m5; bvec = i + 1280; }
        if (m6 > best) { best = m6; bvec = i + 1536; }
        if (m7 > best) { best = m7; bvec = i + 1792; }
    }
    // Tier 2: 4-deep
    for (; i + 3 * 256 < M4; i += 4 * 256) {
        float4 v0 = __ldcs(&rp[i]);
        float4 v1 = __ldcs(&rp[i + 256]);
        float4 v2 = __ldcs(&rp[i + 512]);
        float4 v3 = __ldcs(&rp[i + 768]);
        float m0 = fmaxf(fmaxf(v0.x, v0.y), fmaxf(v0.z, v0.w));
        float m1 = fmaxf(fmaxf(v1.x, v1.y), fmaxf(v1.z, v1.w));
        float m2 = fmaxf(fmaxf(v2.x, v2.y), fmaxf(v2.z, v2.w));
        float m3 = fmaxf(fmaxf(v3.x, v3.y), fmaxf(v3.z, v3.w));
        if (m0 > best) { best = m0; bvec = i;       }
        if (m1 > best) { best = m1; bvec = i + 256; }
        if (m2 > best) { best = m2; bvec = i + 512; }
        if (m3 > best) { best = m3; bvec = i + 768; }
    }
    // Tier 3: remainder
    for (; i < M4; i += 256) {
        float4 v = __ldcs(&rp[i]);
        float m = fmaxf(fmaxf(v.x, v.y), fmaxf(v.z, v.w));
        if (m > best) { best = m; bvec = i; }
    }

    // Recover lane within winning vector (first equality = smallest index).
    // best is bit-identical to one of the 4 elements, so '==' is exact.
    // Plain (caching) load: this row just streamed through this SM; hot.
    {
        float4 v = rp[bvec];
        int b = bvec * 4;
        int bidx = b + 3;
        if (v.z == best) bidx = b + 2;
        if (v.y == best) bidx = b + 1;
        if (v.x == best) bidx = b;
        bvec = bidx;
    }
    int bidx = bvec;

    // Warp reduce (tie-break: smaller index wins on equal value)
    #pragma unroll
    for (int off = 16; off > 0; off >>= 1) {
        float ov = __shfl_down_sync(0xFFFFFFFFu, best, off);
        int   oi = __shfl_down_sync(0xFFFFFFFFu, bidx, off);
        if (ov > best || (ov == best && oi < bidx)) { best = ov; bidx = oi; }
    }

    // Block reduce across 8 warps
    __shared__ float s_val[8];
    __shared__ int   s_idx[8];
    const int wid = threadIdx.x >> 5;
    const int lid = threadIdx.x & 31;
    if (lid == 0) { s_val[wid] = best; s_idx[wid] = bidx; }
    __syncthreads();
    if (wid == 0) {
        best = (lid < 8) ? s_val[lid] : -CUDART_INF_F;
        bidx = (lid < 8) ? s_idx[lid] : 0x7FFFFFFF;
        #pragma unroll
        for (int off = 4; off > 0; off >>= 1) {
            float ov = __shfl_down_sync(0xFFFFFFFFu, best, off);
            int   oi = __shfl_down_sync(0xFFFFFFFFu, bidx, off);
            if (ov > best || (ov == best && oi < bidx)) { best = ov; bidx = oi; }
        }
        if (lid == 0) out_idx[row] = bidx;
    }
}

// Merged launch: blocks [0, NROWS) do the big Substitute rows (scheduled
// first to minimize the tail), blocks [NROWS, 2*NROWS) do Recommended rows.
__global__ void __launch_bounds__(256) argmax_both_kernel(
    const float* __restrict__ rec, const float* __restrict__ sub,
    int* __restrict__ ri, int* __restrict__ si)
{
    if (blockIdx.x < NROWS)
        row_argmax<M_SUB>(sub, blockIdx.x, si);
    else
        row_argmax<M_REC>(rec, blockIdx.x - NROWS, ri);
}

// ---------------------------------------------------------------------------
// Gathers: p_self, Tprefer (out[0:N]), Thaptic (out[2N:3N])
// NOTE: Vid is int32 on-device (JAX default config downcasts jnp.int64).
// ---------------------------------------------------------------------------
__global__ void gather_kernel(const float* __restrict__ preference,
                              const float* __restrict__ structure,
                              const int* __restrict__ Vid,
                              float* __restrict__ out)
{
    const int i = blockIdx.x * blockDim.x + threadIdx.x;
    if (i >= NROWS) return;
    const int r = g_ri[i];
    const int s = g_si[i];
    const float ps = __ldg(&preference[(size_t)s * NROWS + i]);
    g_pself[i] = ps;
    const int v = Vid[MAXG + r];                 // vid_s[ri[i]], 0 <= v < P
    const float po = __ldg(&preference[(size_t)v * NROWS + i]);
    out[i] = ps - po;                                              // Tprefer
    out[2 * NROWS + i] = __ldg(&structure[(size_t)s * M_REC + r]); // Thaptic
}

// ---------------------------------------------------------------------------
// Tsocial fused (out[N:2N]): 128 blocks x 256 threads, 32 i per block,
// 8 threads per i. Whole (si, p_self) table (32 KB) in shared.
// Each sub-lane scans j == sub (mod 8): the warp's 8 subs hit 8 consecutive
// int2s (64 contiguous bytes) per step -> conflict-free LDS.64 with 4-way
// broadcast across i-groups. Fixed shfl tree -> deterministic.
// ---------------------------------------------------------------------------
__global__ void __launch_bounds__(256) tsocial_kernel(float* __restrict__ out)
{
    __shared__ int2 sj[NROWS];   // 32 KB
    for (int j = threadIdx.x; j < NROWS; j += 256)
        sj[j] = make_int2(g_si[j], __float_as_int(g_pself[j]));
    __syncthreads();

    const int i_local = threadIdx.x >> 3;       // 0..31
    const int sub     = threadIdx.x & 7;        // 0..7
    const int i       = blockIdx.x * 32 + i_local;

    const int   si_i = sj[i].x;
    const float p_i  = __int_as_float(sj[i].y);

    float acc = 0.0f;
    #pragma unroll 8
    for (int k = 0; k < NROWS / 8; k++) {
        const int2 v = sj[k * 8 + sub];
        if (v.x == si_i) acc += fminf(p_i, __int_as_float(v.y));
    }

    // Reduce the 8 sub-lanes of this i (consecutive lanes in the warp).
    #pragma unroll
    for (int off = 4; off > 0; off >>= 1)
        acc += __shfl_down_sync(0xFFFFFFFFu, acc, off);

    // Scan included j == i (si_i == si_i always); fminf(p_i, p_i) == p_i.
    if (sub == 0) out[NROWS + i] = acc - p_i;
}

// ---------------------------------------------------------------------------
extern "C" void kernel_launch(void* const* d_in, const int* in_sizes, int n_in,
                              void* d_out, int out_size)
{
    const float* Recommended_m = (const float*)d_in[0];
    const float* Substitute_m  = (const float*)d_in[1];
    // d_in[2] ItemGroups_m : unused
    const int*   Vid           = (const int*)d_in[3];
    // d_in[4..7] VUU/KUU/Vscore/Kscore : unused
    const float* preference    = (const float*)d_in[8];
    const float* structure     = (const float*)d_in[9];
    float* out = (float*)d_out;

    int* d_ri; int* d_si;
    cudaGetSymbolAddress((void**)&d_ri, g_ri);
    cudaGetSymbolAddress((void**)&d_si, g_si);

    argmax_both_kernel<<<2 * NROWS, 256>>>(Recommended_m, Substitute_m, d_ri, d_si);
    gather_kernel<<<(NROWS + 255) / 256, 256>>>(preference, structure, Vid, out);
    tsocial_kernel<<<NROWS / 32, 256>>>(out);
}

// round 10
// speedup vs baseline: 1.0713x; 1.0713x over previous
#include <cuda_runtime.h>
#include <math_constants.h>

#define NROWS 4096
#define M_REC 4000
#define M_SUB 20000
#define MAXG  10

// Scratch (allocation-free per harness rules)
__device__ int g_ri[NROWS];
__device__ int g_si[NROWS];

// ---------------------------------------------------------------------------
// Row argmax: one block per row, float4 vectorized, 4-deep load batch.
// Scan carries only (best value, best VECTOR index) -> dependent chain is
// 2 ops per 16B. Lane within the winning vector recovered post-scan with one
// cache-hot reload (exact bit equality; no arithmetic on best).
// Tie-break: first (smallest) index, matching jnp.argmax.
// ---------------------------------------------------------------------------
template <int M>
__device__ __forceinline__ void row_argmax(const float* __restrict__ mat,
                                           int row, int* __restrict__ out_idx)
{
    const float4* __restrict__ rp =
        reinterpret_cast<const float4*>(mat + (size_t)row * M);
    constexpr int M4 = M / 4;   // both 4000 and 20000 divisible by 4

    float best = -CUDART_INF_F;
    int   bvec = (threadIdx.x < M4) ? (int)threadIdx.x : 0;

    int i = threadIdx.x;
    // 4 independent float4 loads + 4 independent max-trees per iteration
    for (; i + 3 * 256 < M4; i += 4 * 256) {
        float4 v0 = rp[i];
        float4 v1 = rp[i + 256];
        float4 v2 = rp[i + 512];
        float4 v3 = rp[i + 768];
        float m0 = fmaxf(fmaxf(v0.x, v0.y), fmaxf(v0.z, v0.w));
        float m1 = fmaxf(fmaxf(v1.x, v1.y), fmaxf(v1.z, v1.w));
        float m2 = fmaxf(fmaxf(v2.x, v2.y), fmaxf(v2.z, v2.w));
        float m3 = fmaxf(fmaxf(v3.x, v3.y), fmaxf(v3.z, v3.w));
        // strict '>' keeps the earliest vector on ties (ascending visit order)
        if (m0 > best) { best = m0; bvec = i;       }
        if (m1 > best) { best = m1; bvec = i + 256; }
        if (m2 > best) { best = m2; bvec = i + 512; }
        if (m3 > best) { best = m3; bvec = i + 768; }
    }
    for (; i < M4; i += 256) {
        float4 v = rp[i];
        float m = fmaxf(fmaxf(v.x, v.y), fmaxf(v.z, v.w));
        if (m > best) { best = m; bvec = i; }
    }

    // Recover lane within winning vector (first equality = smallest index).
    // best is bit-identical to one of the 4 elements, so '==' is exact.
    {
        float4 v = rp[bvec];
        int b = bvec * 4;
        int bidx = b + 3;
        if (v.z == best) bidx = b + 2;
        if (v.y == best) bidx = b + 1;
        if (v.x == best) bidx = b;
        bvec = bidx;
    }
    int bidx = bvec;

    // Warp reduce (tie-break: smaller index wins on equal value)
    #pragma unroll
    for (int off = 16; off > 0; off >>= 1) {
        float ov = __shfl_down_sync(0xFFFFFFFFu, best, off);
        int   oi = __shfl_down_sync(0xFFFFFFFFu, bidx, off);
        if (ov > best || (ov == best && oi < bidx)) { best = ov; bidx = oi; }
    }

    // Block reduce across 8 warps
    __shared__ float s_val[8];
    __shared__ int   s_idx[8];
    const int wid = threadIdx.x >> 5;
    const int lid = threadIdx.x & 31;
    if (lid == 0) { s_val[wid] = best; s_idx[wid] = bidx; }
    __syncthreads();
    if (wid == 0) {
        best = (lid < 8) ? s_val[lid] : -CUDART_INF_F;
        bidx = (lid < 8) ? s_idx[lid] : 0x7FFFFFFF;
        #pragma unroll
        for (int off = 4; off > 0; off >>= 1) {
            float ov = __shfl_down_sync(0xFFFFFFFFu, best, off);
            int   oi = __shfl_down_sync(0xFFFFFFFFu, bidx, off);
            if (ov > best || (ov == best && oi < bidx)) { best = ov; bidx = oi; }
        }
        if (lid == 0) out_idx[row] = bidx;
    }
}

// Merged launch: blocks [0, NROWS) do the big Substitute rows (scheduled
// first to minimize the tail), blocks [NROWS, 2*NROWS) do Recommended rows.
__global__ void __launch_bounds__(256) argmax_both_kernel(
    const float* __restrict__ rec, const float* __restrict__ sub,
    int* __restrict__ ri, int* __restrict__ si)
{
    if (blockIdx.x < NROWS)
        row_argmax<M_SUB>(sub, blockIdx.x, si);
    else
        row_argmax<M_REC>(rec, blockIdx.x - NROWS, ri);
}

// ---------------------------------------------------------------------------
// Fused tail: p_self gather + Tsocial + Tprefer + Thaptic in ONE kernel.
// 128 blocks x 256 threads, 32 i per block, 8 threads per i.
//
// Phase 1: each block builds the full (si, p_self) table in shared (32 KB).
//   si read is coalesced; preference[si[j]*N + j] gather touches only ~4096
//   unique 32B sectors chip-wide -> blocks beyond the first hit L2.
// Phase 2: Tsocial scan. Each sub-lane scans j == sub (mod 8): the warp's 8
//   subs hit 8 consecutive int2s (64 contiguous bytes) -> conflict-free
//   LDS.64 with 4-way broadcast across i-groups. Fixed shfl tree.
// Phase 3: sub==0 lanes write Tsocial, Tprefer, Thaptic for their i.
// NOTE: Vid is int32 on-device (JAX default config downcasts jnp.int64).
// ---------------------------------------------------------------------------
__global__ void __launch_bounds__(256) tail_fused_kernel(
    const float* __restrict__ preference,
    const float* __restrict__ structure,
    const int*   __restrict__ Vid,
    float* __restrict__ out)
{
    __shared__ int2 sj[NROWS];   // 32 KB: {si, p_self} per j

    // Phase 1: build table (independent iterations -> pipelined gathers)
    #pragma unroll 4
    for (int j = threadIdx.x; j < NROWS; j += 256) {
        const int s = g_si[j];
        const float p = __ldg(&preference[(size_t)s * NROWS + j]);
        sj[j] = make_int2(s, __float_as_int(p));
    }
    __syncthreads();

    const int i_local = threadIdx.x >> 3;       // 0..31
    const int sub     = threadIdx.x & 7;        // 0..7
    const int i       = blockIdx.x * 32 + i_local;

    const int   si_i = sj[i].x;
    const float p_i  = __int_as_float(sj[i].y);

    // Phase 2: Tsocial scan over this thread's j-subset
    float acc = 0.0f;
    #pragma unroll 8
    for (int k = 0; k < NROWS / 8; k++) {
        const int2 v = sj[k * 8 + sub];
        if (v.x == si_i) acc += fminf(p_i, __int_as_float(v.y));
    }

    // Reduce the 8 sub-lanes of this i (consecutive lanes in the warp).
    #pragma unroll
    for (int off = 4; off > 0; off >>= 1)
        acc += __shfl_down_sync(0xFFFFFFFFu, acc, off);

    // Phase 3: outputs for this i
    if (sub == 0) {
        // Scan included j == i (si_i == si_i always); fminf(p_i,p_i) == p_i.
        out[NROWS + i] = acc - p_i;                                 // Tsocial
        const int r = g_ri[i];
        const int v = Vid[MAXG + r];            // vid_s[ri[i]], 0 <= v < P
        const float po = __ldg(&preference[(size_t)v * NROWS + i]);
        out[i] = p_i - po;                                          // Tprefer
        out[2 * NROWS + i] =
            __ldg(&structure[(size_t)si_i * M_REC + r]);            // Thaptic
    }
}

// ---------------------------------------------------------------------------
extern "C" void kernel_launch(void* const* d_in, const int* in_sizes, int n_in,
                              void* d_out, int out_size)
{
    const float* Recommended_m = (const float*)d_in[0];
    const float* Substitute_m  = (const float*)d_in[1];
    // d_in[2] ItemGroups_m : unused
    const int*   Vid           = (const int*)d_in[3];
    // d_in[4..7] VUU/KUU/Vscore/Kscore : unused
    const float* preference    = (const float*)d_in[8];
    const float* structure     = (const float*)d_in[9];
    float* out = (float*)d_out;

    int* d_ri; int* d_si;
    cudaGetSymbolAddress((void**)&d_ri, g_ri);
    cudaGetSymbolAddress((void**)&d_si, g_si);

    argmax_both_kernel<<<2 * NROWS, 256>>>(Recommended_m, Substitute_m, d_ri, d_si);
    tail_fused_kernel<<<NROWS / 32, 256>>>(preference, structure, Vid, out);
}

// round 11
// speedup vs baseline: 1.0769x; 1.0052x over previous
#include <cuda_runtime.h>
#include <math_constants.h>

#define NROWS 4096
#define M_REC 4000
#define M_SUB 20000
#define MAXG  10

// Scratch (allocation-free per harness rules)
__device__ int g_ri[NROWS];
__device__ int g_si[NROWS];

// ---------------------------------------------------------------------------
// Row argmax: one block per row, float4 vectorized, 4-deep load batch.
// Scan carries only (best value, best VECTOR index) -> dependent chain is
// 2 ops per 16B. Lane within the winning vector recovered post-scan with one
// cache-hot reload (exact bit equality; no arithmetic on best).
// Tie-break: first (smallest) index, matching jnp.argmax.
// ---------------------------------------------------------------------------
template <int M>
__device__ __forceinline__ void row_argmax(const float* __restrict__ mat,
                                           int row, int* __restrict__ out_idx)
{
    const float4* __restrict__ rp =
        reinterpret_cast<const float4*>(mat + (size_t)row * M);
    constexpr int M4 = M / 4;   // both 4000 and 20000 divisible by 4

    float best = -CUDART_INF_F;
    int   bvec = (threadIdx.x < M4) ? (int)threadIdx.x : 0;

    int i = threadIdx.x;
    // 4 independent float4 loads + 4 independent max-trees per iteration
    for (; i + 3 * 256 < M4; i += 4 * 256) {
        float4 v0 = rp[i];
        float4 v1 = rp[i + 256];
        float4 v2 = rp[i + 512];
        float4 v3 = rp[i + 768];
        float m0 = fmaxf(fmaxf(v0.x, v0.y), fmaxf(v0.z, v0.w));
        float m1 = fmaxf(fmaxf(v1.x, v1.y), fmaxf(v1.z, v1.w));
        float m2 = fmaxf(fmaxf(v2.x, v2.y), fmaxf(v2.z, v2.w));
        float m3 = fmaxf(fmaxf(v3.x, v3.y), fmaxf(v3.z, v3.w));
        // strict '>' keeps the earliest vector on ties (ascending visit order)
        if (m0 > best) { best = m0; bvec = i;       }
        if (m1 > best) { best = m1; bvec = i + 256; }
        if (m2 > best) { best = m2; bvec = i + 512; }
        if (m3 > best) { best = m3; bvec = i + 768; }
    }
    for (; i < M4; i += 256) {
        float4 v = rp[i];
        float m = fmaxf(fmaxf(v.x, v.y), fmaxf(v.z, v.w));
        if (m > best) { best = m; bvec = i; }
    }

    // Recover lane within winning vector (first equality = smallest index).
    // best is bit-identical to one of the 4 elements, so '==' is exact.
    {
        float4 v = rp[bvec];
        int b = bvec * 4;
        int bidx = b + 3;
        if (v.z == best) bidx = b + 2;
        if (v.y == best) bidx = b + 1;
        if (v.x == best) bidx = b;
        bvec = bidx;
    }
    int bidx = bvec;

    // Warp reduce (tie-break: smaller index wins on equal value)
    #pragma unroll
    for (int off = 16; off > 0; off >>= 1) {
        float ov = __shfl_down_sync(0xFFFFFFFFu, best, off);
        int   oi = __shfl_down_sync(0xFFFFFFFFu, bidx, off);
        if (ov > best || (ov == best && oi < bidx)) { best = ov; bidx = oi; }
    }

    // Block reduce across 8 warps
    __shared__ float s_val[8];
    __shared__ int   s_idx[8];
    const int wid = threadIdx.x >> 5;
    const int lid = threadIdx.x & 31;
    if (lid == 0) { s_val[wid] = best; s_idx[wid] = bidx; }
    __syncthreads();
    if (wid == 0) {
        best = (lid < 8) ? s_val[lid] : -CUDART_INF_F;
        bidx = (lid < 8) ? s_idx[lid] : 0x7FFFFFFF;
        #pragma unroll
        for (int off = 4; off > 0; off >>= 1) {
            float ov = __shfl_down_sync(0xFFFFFFFFu, best, off);
            int   oi = __shfl_down_sync(0xFFFFFFFFu, bidx, off);
            if (ov > best || (ov == best && oi < bidx)) { best = ov; bidx = oi; }
        }
        if (lid == 0) out_idx[row] = bidx;
    }
}

// Merged launch: blocks [0, NROWS) do the big Substitute rows (scheduled
// first to minimize the tail), blocks [NROWS, 2*NROWS) do Recommended rows.
__global__ void __launch_bounds__(256) argmax_both_kernel(
    const float* __restrict__ rec, const float* __restrict__ sub,
    int* __restrict__ ri, int* __restrict__ si)
{
    if (blockIdx.x < NROWS)
        row_argmax<M_SUB>(sub, blockIdx.x, si);
    else
        row_argmax<M_REC>(rec, blockIdx.x - NROWS, ri);
}

// ---------------------------------------------------------------------------
// Fused tail: p_self gather + Tsocial + Tprefer + Thaptic in ONE kernel.
// 128 blocks x 256 threads, 32 i per block, 8 threads per i.
//
// Phase 1 (latency-critical, cold L2 at replay time): three fully-unrolled
//   passes so all 16 per-thread load chains are in flight simultaneously
//   (MLP=16/thread, 128/SM): (a) 16 coalesced si loads, (b) 16 independent
//   scattered preference gathers, (c) 16 conflict-free smem stores.
// Phase 2: Tsocial scan. Each sub-lane scans j == sub (mod 8): the warp's 8
//   subs hit 8 consecutive int2s (64 contiguous bytes) -> conflict-free
//   LDS.64 with 4-way broadcast across i-groups. Fixed shfl tree.
// Phase 3: sub==0 lanes write Tsocial, Tprefer, Thaptic for their i.
// NOTE: Vid is int32 on-device (JAX default config downcasts jnp.int64).
// ---------------------------------------------------------------------------
__global__ void __launch_bounds__(256) tail_fused_kernel(
    const float* __restrict__ preference,
    const float* __restrict__ structure,
    const int*   __restrict__ Vid,
    float* __restrict__ out)
{
    __shared__ int2 sj[NROWS];   // 32 KB: {si, p_self} per j
    constexpr int K16 = NROWS / 256;   // 16 j-slots per thread

    // Phase 1a: 16 independent coalesced si loads
    int s[K16];
    #pragma unroll
    for (int k = 0; k < K16; k++)
        s[k] = g_si[threadIdx.x + k * 256];
    // Phase 1b: 16 independent scattered gathers (all chains overlap)
    float p[K16];
    #pragma unroll
    for (int k = 0; k < K16; k++)
        p[k] = __ldg(&preference[(size_t)s[k] * NROWS + threadIdx.x + k * 256]);
    // Phase 1c: conflict-free interleaved smem stores
    #pragma unroll
    for (int k = 0; k < K16; k++)
        sj[threadIdx.x + k * 256] = make_int2(s[k], __float_as_int(p[k]));
    __syncthreads();

    const int i_local = threadIdx.x >> 3;       // 0..31
    const int sub     = threadIdx.x & 7;        // 0..7
    const int i       = blockIdx.x * 32 + i_local;

    const int   si_i = sj[i].x;
    const float p_i  = __int_as_float(sj[i].y);

    // Phase 2: Tsocial scan over this thread's j-subset
    float acc = 0.0f;
    #pragma unroll 8
    for (int k = 0; k < NROWS / 8; k++) {
        const int2 v = sj[k * 8 + sub];
        if (v.x == si_i) acc += fminf(p_i, __int_as_float(v.y));
    }

    // Reduce the 8 sub-lanes of this i (consecutive lanes in the warp).
    #pragma unroll
    for (int off = 4; off > 0; off >>= 1)
        acc += __shfl_down_sync(0xFFFFFFFFu, acc, off);

    // Phase 3: outputs for this i
    if (sub == 0) {
        // Scan included j == i (si_i == si_i always); fminf(p_i,p_i) == p_i.
        out[NROWS + i] = acc - p_i;                                 // Tsocial
        const int r = g_ri[i];
        const int v = Vid[MAXG + r];            // vid_s[ri[i]], 0 <= v < P
        const float po = __ldg(&preference[(size_t)v * NROWS + i]);
        out[i] = p_i - po;                                          // Tprefer
        out[2 * NROWS + i] =
            __ldg(&structure[(size_t)si_i * M_REC + r]);            // Thaptic
    }
}

// ---------------------------------------------------------------------------
extern "C" void kernel_launch(void* const* d_in, const int* in_sizes, int n_in,
                              void* d_out, int out_size)
{
    const float* Recommended_m = (const float*)d_in[0];
    const float* Substitute_m  = (const float*)d_in[1];
    // d_in[2] ItemGroups_m : unused
    const int*   Vid           = (const int*)d_in[3];
    // d_in[4..7] VUU/KUU/Vscore/Kscore : unused
    const float* preference    = (const float*)d_in[8];
    const float* structure     = (const float*)d_in[9];
    float* out = (float*)d_out;

    int* d_ri; int* d_si;
    cudaGetSymbolAddress((void**)&d_ri, g_ri);
    cudaGetSymbolAddress((void**)&d_si, g_si);

    argmax_both_kernel<<<2 * NROWS, 256>>>(Recommended_m, Substitute_m, d_ri, d_si);
    tail_fused_kernel<<<NROWS / 32, 256>>>(preference, structure, Vid, out);
}

// round 12
// speedup vs baseline: 1.1590x; 1.0763x over previous
#include <cuda_runtime.h>
#include <math_constants.h>

#define NROWS 4096
#define M_REC 4000
#define M_SUB 20000
#define MAXG  10

// Scratch (allocation-free per harness rules)
__device__ int  g_ri[NROWS];
__device__ int  g_si[NROWS];
__device__ int2 g_tab[NROWS];   // {si, p_self} per j

// ---------------------------------------------------------------------------
// Row argmax: one block per row, float4 vectorized, 4-deep load batch.
// (Best-measured config; do not touch.) Tie-break matches jnp.argmax.
// ---------------------------------------------------------------------------
template <int M>
__device__ __forceinline__ void row_argmax(const float* __restrict__ mat,
                                           int row, int* __restrict__ out_idx)
{
    const float4* __restrict__ rp =
        reinterpret_cast<const float4*>(mat + (size_t)row * M);
    constexpr int M4 = M / 4;   // both 4000 and 20000 divisible by 4

    float best = -CUDART_INF_F;
    int   bvec = (threadIdx.x < M4) ? (int)threadIdx.x : 0;

    int i = threadIdx.x;
    for (; i + 3 * 256 < M4; i += 4 * 256) {
        float4 v0 = rp[i];
        float4 v1 = rp[i + 256];
        float4 v2 = rp[i + 512];
        float4 v3 = rp[i + 768];
        float m0 = fmaxf(fmaxf(v0.x, v0.y), fmaxf(v0.z, v0.w));
        float m1 = fmaxf(fmaxf(v1.x, v1.y), fmaxf(v1.z, v1.w));
        float m2 = fmaxf(fmaxf(v2.x, v2.y), fmaxf(v2.z, v2.w));
        float m3 = fmaxf(fmaxf(v3.x, v3.y), fmaxf(v3.z, v3.w));
        // strict '>' keeps the earliest vector on ties (ascending visit order)
        if (m0 > best) { best = m0; bvec = i;       }
        if (m1 > best) { best = m1; bvec = i + 256; }
        if (m2 > best) { best = m2; bvec = i + 512; }
        if (m3 > best) { best = m3; bvec = i + 768; }
    }
    for (; i < M4; i += 256) {
        float4 v = rp[i];
        float m = fmaxf(fmaxf(v.x, v.y), fmaxf(v.z, v.w));
        if (m > best) { best = m; bvec = i; }
    }

    // Recover lane within winning vector (first equality = smallest index).
    {
        float4 v = rp[bvec];
        int b = bvec * 4;
        int bidx = b + 3;
        if (v.z == best) bidx = b + 2;
        if (v.y == best) bidx = b + 1;
        if (v.x == best) bidx = b;
        bvec = bidx;
    }
    int bidx = bvec;

    #pragma unroll
    for (int off = 16; off > 0; off >>= 1) {
        float ov = __shfl_down_sync(0xFFFFFFFFu, best, off);
        int   oi = __shfl_down_sync(0xFFFFFFFFu, bidx, off);
        if (ov > best || (ov == best && oi < bidx)) { best = ov; bidx = oi; }
    }

    __shared__ float s_val[8];
    __shared__ int   s_idx[8];
    const int wid = threadIdx.x >> 5;
    const int lid = threadIdx.x & 31;
    if (lid == 0) { s_val[wid] = best; s_idx[wid] = bidx; }
    __syncthreads();
    if (wid == 0) {
        best = (lid < 8) ? s_val[lid] : -CUDART_INF_F;
        bidx = (lid < 8) ? s_idx[lid] : 0x7FFFFFFF;
        #pragma unroll
        for (int off = 4; off > 0; off >>= 1) {
            float ov = __shfl_down_sync(0xFFFFFFFFu, best, off);
            int   oi = __shfl_down_sync(0xFFFFFFFFu, bidx, off);
            if (ov > best || (ov == best && oi < bidx)) { best = ov; bidx = oi; }
        }
        if (lid == 0) out_idx[row] = bidx;
    }
}

__global__ void __launch_bounds__(256) argmax_both_kernel(
    const float* __restrict__ rec, const float* __restrict__ sub,
    int* __restrict__ ri, int* __restrict__ si)
{
    if (blockIdx.x < NROWS)
        row_argmax<M_SUB>(sub, blockIdx.x, si);
    else
        row_argmax<M_REC>(rec, blockIdx.x - NROWS, ri);
}

// ---------------------------------------------------------------------------
// Prep: ALL scattered/latency work, once, with 4096-way parallelism.
// One thread per j: builds g_tab[j] = {si[j], p_self[j]}, writes Tprefer
// (out[0:N]) and Thaptic (out[2N:3N]). Three dependent load rounds, each
// round fully parallel chip-wide:
//   round 1: si[j], ri[j]              (coalesced)
//   round 2: preference[s*N+j], Vid[10+r]
//   round 3: preference[v*N+j], structure[s*M_REC+r]
// NOTE: Vid is int32 on-device (JAX default config downcasts jnp.int64).
// ---------------------------------------------------------------------------
__global__ void __launch_bounds__(128) prep_kernel(
    const float* __restrict__ preference,
    const float* __restrict__ structure,
    const int*   __restrict__ Vid,
    float* __restrict__ out)
{
    const int j = blockIdx.x * 128 + threadIdx.x;
    // round 1 (independent)
    const int s = g_si[j];
    const int r = g_ri[j];
    // round 2 (independent of each other)
    const float p = __ldg(&preference[(size_t)s * NROWS + j]);
    const int   v = Vid[MAXG + r];          // vid_s[ri[j]], 0 <= v < P
    // round 3 (independent of each other)
    const float po = __ldg(&preference[(size_t)v * NROWS + j]);
    const float th = __ldg(&structure[(size_t)s * M_REC + r]);

    g_tab[j] = make_int2(s, __float_as_int(p));
    out[j] = p - po;                        // Tprefer
    out[2 * NROWS + j] = th;                // Thaptic
}

// ---------------------------------------------------------------------------
// Tsocial (out[N:2N]): 128 blocks x 512 threads, 32 i per block, 16 subs
// per i. Table loaded coalesced from g_tab (32 KB unique -> L2-hot after
// the first wave). Scan: addr = k*16+sub -> a warp's 16 sub-lanes read 16
// consecutive int2 (128 B, exactly 32 banks, conflict-free) with 2x
// broadcast across its 2 i-groups. 16 warps/SM hide LDS latency.
// Fixed shfl tree -> deterministic.
// ---------------------------------------------------------------------------
__global__ void __launch_bounds__(512) tsocial_kernel(float* __restrict__ out)
{
    __shared__ int2 sj[NROWS];   // 32 KB

    // Coalesced table load: 8 slots per thread, all independent.
    #pragma unroll
    for (int k = 0; k < NROWS / 512; k++)
        sj[threadIdx.x + k * 512] = g_tab[threadIdx.x + k * 512];
    __syncthreads();

    const int i_local = threadIdx.x >> 4;       // 0..31
    const int sub     = threadIdx.x & 15;       // 0..15
    const int i       = blockIdx.x * 32 + i_local;

    const int   si_i = sj[i].x;
    const float p_i  = __int_as_float(sj[i].y);

    float acc = 0.0f;
    #pragma unroll 8
    for (int k = 0; k < NROWS / 16; k++) {
        const int2 v = sj[k * 16 + sub];
        if (v.x == si_i) acc += fminf(p_i, __int_as_float(v.y));
    }

    // Reduce the 16 sub-lanes of this i (consecutive lanes in the warp).
    #pragma unroll
    for (int off = 8; off > 0; off >>= 1)
        acc += __shfl_down_sync(0xFFFFFFFFu, acc, off);

    // Scan included j == i (si_i == si_i always); fminf(p_i, p_i) == p_i.
    if (sub == 0) out[NROWS + i] = acc - p_i;
}

// ---------------------------------------------------------------------------
extern "C" void kernel_launch(void* const* d_in, const int* in_sizes, int n_in,
                              void* d_out, int out_size)
{
    const float* Recommended_m = (const float*)d_in[0];
    const float* Substitute_m  = (const float*)d_in[1];
    // d_in[2] ItemGroups_m : unused
    const int*   Vid           = (const int*)d_in[3];
    // d_in[4..7] VUU/KUU/Vscore/Kscore : unused
    const float* preference    = (const float*)d_in[8];
    const float* structure     = (const float*)d_in[9];
    float* out = (float*)d_out;

    int* d_ri; int* d_si;
    cudaGetSymbolAddress((void**)&d_ri, g_ri);
    cudaGetSymbolAddress((void**)&d_si, g_si);

    argmax_both_kernel<<<2 * NROWS, 256>>>(Recommended_m, Substitute_m, d_ri, d_si);
    prep_kernel<<<NROWS / 128, 128>>>(preference, structure, Vid, out);
    tsocial_kernel<<<NROWS / 32, 512>>>(out);
}